// round 5
// baseline (speedup 1.0000x reference)
#include <cuda_runtime.h>
#include <cstdint>

// ---------------- Problem constants ----------------
#define NB    4096
#define SEQ   168
#define PRED  96
#define CF    64      // channels
#define KK    25      // decomp kernel taps
#define PAD   12
#define NQ    4
#define NL    3
#define NLAG  11

// ---------------- Scratch (device globals; no allocation) ----------------
__device__ float4 g_G4[PRED * SEQ * (CF / 4)];   // G[p][j][c] as float4 over c
__device__ float4 g_H4[PRED * SEQ * (CF / 4)];   // H[p][j][c]
__device__ float  g_mod[NB * PRED];
__device__ float  g_b0[PRED];
__device__ float  g_b1[PRED];

// =====================================================================
// Kernel 1: build folded weight tensors G, H (and biases)
//   G[c,p,j] = a*seasW[p,j] + A(D)[c,p,j],  D = (1-a)*trendW - a*seasW
//   H[c,p,j] = a*(seasW[p,j] - A(seasW)[c,p,j])
//   A(W)[c,p,j] = sum over {(l,k): clamp(l+k-12,0,167)==j} ker[c,k]*W[p,l]
// grid: (ceil(96*168/256)=63, 64 channels), block 256
// =====================================================================
__global__ void qres_prep(const float* __restrict__ dw,
                          const float* __restrict__ tW,
                          const float* __restrict__ tb_,
                          const float* __restrict__ sW,
                          const float* __restrict__ sb_,
                          const float* __restrict__ alpha)
{
    __shared__ float ker[KK];
    const int c = blockIdx.y;
    if (threadIdx.x == 0) {
        float mx = -1e30f;
        for (int k = 0; k < KK; k++) mx = fmaxf(mx, dw[c * KK + k]);
        float s = 0.f;
        for (int k = 0; k < KK; k++) { float v = expf(dw[c * KK + k] - mx); ker[k] = v; s += v; }
        float inv = 1.f / s;
        for (int k = 0; k < KK; k++) ker[k] *= inv;
    }
    __syncthreads();

    const int idx = blockIdx.x * 256 + threadIdx.x;
    if (idx >= PRED * SEQ) return;
    const int p = idx / SEQ;
    const int j = idx - p * SEQ;

    const float a  = 1.f / (1.f + expf(-alpha[0]));
    const float ia = 1.f - a;

    const float* tw = tW + p * SEQ;
    const float* sw = sW + p * SEQ;

    float accD = 0.f, accS = 0.f;
    if (j == 0) {
        #pragma unroll 1
        for (int k = 0; k <= PAD; k++) {
            const float kk = ker[k];
            for (int l = 0; l <= PAD - k; l++) {
                accD += kk * (ia * tw[l] - a * sw[l]);
                accS += kk * sw[l];
            }
        }
    } else if (j == SEQ - 1) {
        #pragma unroll 1
        for (int k = PAD; k < KK; k++) {
            const float kk = ker[k];
            for (int l = (SEQ - 1 + PAD) - k; l < SEQ; l++) {
                accD += kk * (ia * tw[l] - a * sw[l]);
                accS += kk * sw[l];
            }
        }
    } else {
        #pragma unroll
        for (int k = 0; k < KK; k++) {
            const int l = j + PAD - k;
            if (l >= 0 && l < SEQ) {
                const float kk = ker[k];
                accD += kk * (ia * tw[l] - a * sw[l]);
                accS += kk * sw[l];
            }
        }
    }

    float* Gf = reinterpret_cast<float*>(g_G4);
    float* Hf = reinterpret_cast<float*>(g_H4);
    const float swj = sw[j];
    Gf[(p * SEQ + j) * CF + c] = a * swj + accD;
    Hf[(p * SEQ + j) * CF + c] = a * (swj - accS);

    if (blockIdx.y == 0 && idx < PRED) {
        g_b0[idx] = a * sb_[idx] + ia * tb_[idx];
        g_b1[idx] = a * sb_[idx];
    }
}

// =====================================================================
// Kernel 2: quantum circuit + readout MLP -> mod[b][p]
// =====================================================================
__device__ __forceinline__ void circuit_feats(const float* __restrict__ U,  // 12 gates * 8
                                              const float* cry, const float* sry,
                                              int pauli, float* feats)
{
    float sr[16], si[16];
    #pragma unroll
    for (int i = 0; i < 16; i++) { sr[i] = 0.f; si[i] = 0.f; }
    sr[0] = 1.f;

    #pragma unroll
    for (int l = 0; l < NL; l++) {
        // RY(q_in[q]) on each qubit (same angles each layer)
        #pragma unroll
        for (int q = 0; q < NQ; q++) {
            const int m = 8 >> q;
            const float cc = cry[q], ss = sry[q];
            #pragma unroll
            for (int g = 0; g < 8; g++) {
                const int i0 = ((g & ~(m - 1)) << 1) | (g & (m - 1));
                const int i1 = i0 | m;
                const float r0 = sr[i0], r1 = sr[i1];
                const float q0 = si[i0], q1 = si[i1];
                sr[i0] = cc * r0 - ss * r1;  sr[i1] = ss * r0 + cc * r1;
                si[i0] = cc * q0 - ss * q1;  si[i1] = ss * q0 + cc * q1;
            }
        }
        // Rot(phi,theta,omega) on each qubit
        #pragma unroll
        for (int q = 0; q < NQ; q++) {
            const float* u = U + (l * NQ + q) * 8;
            const float u00r = u[0], u00i = u[1], u01r = u[2], u01i = u[3];
            const float u10r = u[4], u10i = u[5], u11r = u[6], u11i = u[7];
            const int m = 8 >> q;
            #pragma unroll
            for (int g = 0; g < 8; g++) {
                const int i0 = ((g & ~(m - 1)) << 1) | (g & (m - 1));
                const int i1 = i0 | m;
                const float a0r = sr[i0], a0i = si[i0];
                const float a1r = sr[i1], a1i = si[i1];
                sr[i0] = u00r * a0r - u00i * a0i + u01r * a1r - u01i * a1i;
                si[i0] = u00r * a0i + u00i * a0r + u01r * a1i + u01i * a1r;
                sr[i1] = u10r * a0r - u10i * a0i + u11r * a1r - u11i * a1i;
                si[i1] = u10r * a0i + u10i * a0r + u11r * a1i + u11i * a1r;
            }
        }
        // CNOT(q, (q+1)%4) in order
        #pragma unroll
        for (int q = 0; q < NQ; q++) {
            const int mc = 8 >> q;
            const int mt = 8 >> ((q + 1) & 3);
            #pragma unroll
            for (int i = 0; i < 16; i++) {
                if ((i & mc) && !(i & mt)) {
                    const int jx = i | mt;
                    float t0 = sr[i]; sr[i] = sr[jx]; sr[jx] = t0;
                    float t1 = si[i]; si[i] = si[jx]; si[jx] = t1;
                }
            }
        }
    }

    #pragma unroll
    for (int q = 0; q < NQ; q++) {
        const int m = 8 >> q;
        float acc = 0.f;
        #pragma unroll
        for (int g = 0; g < 8; g++) {
            const int i0 = ((g & ~(m - 1)) << 1) | (g & (m - 1));
            const int i1 = i0 | m;
            if (pauli == 0)      acc += sr[i0] * sr[i1] + si[i0] * si[i1];           // 2*Re<0|1>
            else if (pauli == 1) acc += sr[i0] * si[i1] - si[i0] * sr[i1];           // 2*Im<0|1>
            else acc += sr[i0] * sr[i0] + si[i0] * si[i0] - sr[i1] * sr[i1] - si[i1] * si[i1];
        }
        feats[q] = (pauli == 2) ? acc : 2.f * acc;
    }
}

__global__ __launch_bounds__(256) void qres_quantum(
    const float* __restrict__ x,
    const float* __restrict__ lW, const float* __restrict__ lb,
    const float* __restrict__ wx, const float* __restrict__ wy, const float* __restrict__ wz,
    const float* __restrict__ W1, const float* __restrict__ b1v,
    const float* __restrict__ W2, const float* __restrict__ b2v)
{
    __shared__ float Us[3][NL * NQ * 8];
    __shared__ float sW1[12 * 12], sb1[12], sW2[96 * 12], sb2[96];

    const int tid = threadIdx.x;
    if (tid < 36) {
        const int t = tid / 12, rem = tid % 12;
        const int l = rem / 4, q = rem % 4;
        const float* w = (t == 0) ? wx : ((t == 1) ? wy : wz);
        const float phi = w[(l * NQ + q) * 3 + 0];
        const float th  = w[(l * NQ + q) * 3 + 1];
        const float om  = w[(l * NQ + q) * 3 + 2];
        float st, ct;  sincosf(0.5f * th, &st, &ct);
        float sap, cap; sincosf(0.5f * (phi + om), &sap, &cap);   // ep = cap - i*sap
        float sam, cam; sincosf(0.5f * (phi - om), &sam, &cam);   // em = cam + i*sam
        float* U = &Us[t][rem * 8];
        U[0] =  cap * ct;  U[1] = -sap * ct;   // U00 = ep*ct
        U[2] = -cam * st;  U[3] = -sam * st;   // U01 = -em*st
        U[4] =  cam * st;  U[5] = -sam * st;   // U10 = conj(em)*st
        U[6] =  cap * ct;  U[7] =  sap * ct;   // U11 = conj(ep)*ct
    }
    for (int i = tid; i < 144;  i += 256) sW1[i] = W1[i];
    for (int i = tid; i < 1152; i += 256) sW2[i] = W2[i];
    if (tid < 12) sb1[tid] = b1v[tid];
    if (tid < 96) sb2[tid] = b2v[tid];
    __syncthreads();

    const int b = blockIdx.x * 256 + tid;
    if (b >= NB) return;

    // lag features: x[b, LAG_IDX, channel 63]
    const int LAGS[NLAG] = {167, 166, 165, 164, 163, 162, 145, 144, 143, 1, 0};
    float lag[NLAG];
    const float* xb = x + (size_t)b * SEQ * CF + (CF - 1);
    #pragma unroll
    for (int i = 0; i < NLAG; i++) lag[i] = xb[LAGS[i] * CF];

    const float PI_F = 3.14159265358979323846f;
    float cry[NQ], sry[NQ];
    #pragma unroll
    for (int q = 0; q < NQ; q++) {
        float acc = lb[q];
        #pragma unroll
        for (int i = 0; i < NLAG; i++) acc += lag[i] * lW[q * NLAG + i];
        const float qin = tanhf(acc) * PI_F;
        sincosf(0.5f * qin, &sry[q], &cry[q]);
    }

    float feats[12];
    circuit_feats(&Us[0][0], cry, sry, 0, &feats[0]);
    circuit_feats(&Us[1][0], cry, sry, 1, &feats[4]);
    circuit_feats(&Us[2][0], cry, sry, 2, &feats[8]);

    float h[12];
    #pragma unroll
    for (int i = 0; i < 12; i++) {
        float acc = sb1[i];
        #pragma unroll
        for (int jj = 0; jj < 12; jj++) acc += feats[jj] * sW1[i * 12 + jj];
        h[i] = fmaxf(acc, 0.f);
    }
    #pragma unroll 4
    for (int p = 0; p < PRED; p++) {
        float acc = sb2[p];
        #pragma unroll
        for (int i = 0; i < 12; i++) acc += h[i] * sW2[p * 12 + i];
        g_mod[b * PRED + p] = tanhf(acc);
    }
}

// =====================================================================
// Kernel 3: main batched GEMM (channel = float4 SIMD lane)
//   out[b,p,c] = x.G + mod*(x.H) + b0[p] + mod*b1[p]
// Block tile: 64 b x 32 p x 4 c. Threads 256 = 16(b) x 16(p).
// Thread tile: 4 b x 2 p x float4. K-panels of 8, double buffered.
// grid: (3 p-tiles, 16 c-groups, 64 b-tiles)  [b slowest -> x L2 reuse]
// =====================================================================
#define KP 8
#define NPANEL (SEQ / KP)   // 21

__global__ __launch_bounds__(256) void qres_main(const float* __restrict__ x,
                                                 float* __restrict__ out)
{
    const int pt = blockIdx.x;           // 0..2
    const int cg = blockIdx.y;           // 0..15
    const int bt = blockIdx.z;           // 0..63
    const int b0 = bt * 64;
    const int p0 = pt * 32;

    const int tid = threadIdx.x;
    const int tb = tid & 15;             // b-thread
    const int tp = tid >> 4;             // p-thread

    __shared__ float4 Xs[2][KP][64];
    __shared__ float4 Gs[2][KP][32];
    __shared__ float4 Hs[2][KP][32];

    const float4* xg = reinterpret_cast<const float4*>(x);
    const float4* Gg = g_G4;
    const float4* Hg = g_H4;

    float4 aG[4][2], aH[4][2];
    #pragma unroll
    for (int bi = 0; bi < 4; bi++)
        #pragma unroll
        for (int pi = 0; pi < 2; pi++) {
            aG[bi][pi] = make_float4(0.f, 0.f, 0.f, 0.f);
            aH[bi][pi] = make_float4(0.f, 0.f, 0.f, 0.f);
        }

    const int xk0 = tid >> 6;    // 0..3
    const int xb0 = tid & 63;    // 0..63
    const int gk  = tid >> 5;    // 0..7
    const int gp  = tid & 31;    // 0..31

    // prologue: panel 0 -> buffer 0
    {
        const int xbase = ((b0 + xb0) * SEQ + xk0) * (CF / 4) + cg;
        Xs[0][xk0][xb0]     = xg[xbase];
        Xs[0][xk0 + 4][xb0] = xg[xbase + 4 * (CF / 4)];
        const int gbase = ((p0 + gp) * SEQ + gk) * (CF / 4) + cg;
        Gs[0][gk][gp] = Gg[gbase];
        Hs[0][gk][gp] = Hg[gbase];
    }
    __syncthreads();

    for (int pn = 0; pn < NPANEL; pn++) {
        const int buf = pn & 1;
        float4 rx0, rx1, rg, rh;
        const bool more = (pn + 1 < NPANEL);
        if (more) {
            const int j0 = (pn + 1) * KP;
            const int xbase = ((b0 + xb0) * SEQ + j0 + xk0) * (CF / 4) + cg;
            rx0 = xg[xbase];
            rx1 = xg[xbase + 4 * (CF / 4)];
            const int gbase = ((p0 + gp) * SEQ + j0 + gk) * (CF / 4) + cg;
            rg = Gg[gbase];
            rh = Hg[gbase];
        }

        #pragma unroll
        for (int kj = 0; kj < KP; kj++) {
            float4 xf[4], gf[2], hf[2];
            #pragma unroll
            for (int i = 0; i < 4; i++) xf[i] = Xs[buf][kj][tb + 16 * i];
            #pragma unroll
            for (int i = 0; i < 2; i++) { gf[i] = Gs[buf][kj][tp + 16 * i];
                                          hf[i] = Hs[buf][kj][tp + 16 * i]; }
            #pragma unroll
            for (int bi = 0; bi < 4; bi++)
                #pragma unroll
                for (int pi = 0; pi < 2; pi++) {
                    aG[bi][pi].x += xf[bi].x * gf[pi].x;
                    aG[bi][pi].y += xf[bi].y * gf[pi].y;
                    aG[bi][pi].z += xf[bi].z * gf[pi].z;
                    aG[bi][pi].w += xf[bi].w * gf[pi].w;
                    aH[bi][pi].x += xf[bi].x * hf[pi].x;
                    aH[bi][pi].y += xf[bi].y * hf[pi].y;
                    aH[bi][pi].z += xf[bi].z * hf[pi].z;
                    aH[bi][pi].w += xf[bi].w * hf[pi].w;
                }
        }

        if (more) {
            const int nb = buf ^ 1;
            Xs[nb][xk0][xb0]     = rx0;
            Xs[nb][xk0 + 4][xb0] = rx1;
            Gs[nb][gk][gp] = rg;
            Hs[nb][gk][gp] = rh;
            __syncthreads();
        }
    }

    // epilogue
    float4* og = reinterpret_cast<float4*>(out);
    #pragma unroll
    for (int bi = 0; bi < 4; bi++) {
        const int b = b0 + tb + 16 * bi;
        #pragma unroll
        for (int pi = 0; pi < 2; pi++) {
            const int p = p0 + tp + 16 * pi;
            const float m = g_mod[b * PRED + p];
            const float add = g_b0[p] + m * g_b1[p];
            float4 r;
            r.x = aG[bi][pi].x + m * aH[bi][pi].x + add;
            r.y = aG[bi][pi].y + m * aH[bi][pi].y + add;
            r.z = aG[bi][pi].z + m * aH[bi][pi].z + add;
            r.w = aG[bi][pi].w + m * aH[bi][pi].w + add;
            og[((size_t)b * PRED + p) * (CF / 4) + cg] = r;
        }
    }
}

// =====================================================================
// Launch
// metadata order: x, decomp_w, trend_W, trend_b, seas_W, seas_b,
//                 lagc_W, lagc_b, res_wx, res_wy, res_wz,
//                 ro_W1, ro_b1, ro_W2, ro_b2, alpha
// =====================================================================
extern "C" void kernel_launch(void* const* d_in, const int* in_sizes, int n_in,
                              void* d_out, int out_size)
{
    const float* x      = (const float*)d_in[0];
    const float* dw     = (const float*)d_in[1];
    const float* tW     = (const float*)d_in[2];
    const float* tb_    = (const float*)d_in[3];
    const float* sW     = (const float*)d_in[4];
    const float* sb_    = (const float*)d_in[5];
    const float* lagcW  = (const float*)d_in[6];
    const float* lagcb  = (const float*)d_in[7];
    const float* wx     = (const float*)d_in[8];
    const float* wy     = (const float*)d_in[9];
    const float* wz     = (const float*)d_in[10];
    const float* roW1   = (const float*)d_in[11];
    const float* rob1   = (const float*)d_in[12];
    const float* roW2   = (const float*)d_in[13];
    const float* rob2   = (const float*)d_in[14];
    const float* alpha  = (const float*)d_in[15];
    float* out = (float*)d_out;

    qres_prep<<<dim3((PRED * SEQ + 255) / 256, CF), 256>>>(dw, tW, tb_, sW, sb_, alpha);
    qres_quantum<<<NB / 256, 256>>>(x, lagcW, lagcb, wx, wy, wz, roW1, rob1, roW2, rob2);
    qres_main<<<dim3(3, CF / 4, NB / 64), 256>>>(x, out);
}